// round 1
// baseline (speedup 1.0000x reference)
#include <cuda_runtime.h>
#include <math.h>

#define BB   8192
#define SS   200
#define DD   64
#define SROW 201              // odd stride -> conflict-free smem in both phases
#define NEGV (-4294967296.0f) // -2^32

// Precomputed fused parameters (prep kernel output)
__device__ float g_M2t[DD * DD];  // M2t[j*64+d] = sum_i Wk[i,d]*Wq[i,j]  (m = M2 c, coalesced over d)
__device__ float g_mb[DD];        // mb[d] = sum_i Wk[i,d]*bq[i]
__device__ float g_u[DD];         // u[j]  = sum_i Wq[i,j]*bk[i]
__device__ float g_t;             // bq . bk
__device__ float g_F[2 * DD];     // F = Wc @ Wp @ Wv  (2 x 64)
__device__ float g_f0[2];         // f0 = Wc(Wp bv + bp) + bc
__device__ float g_loss[BB];      // per-row loss, deterministic reduce afterwards

__global__ __launch_bounds__(256) void crec_prep(
    const float* __restrict__ Wq, const float* __restrict__ bq,
    const float* __restrict__ Wk, const float* __restrict__ bk,
    const float* __restrict__ Wv, const float* __restrict__ bv,
    const float* __restrict__ Wp, const float* __restrict__ bp,
    const float* __restrict__ Wc, const float* __restrict__ bc)
{
    const int tid = threadIdx.x;
    __shared__ float T[DD * DD];  // Wp @ Wv

    // M2t[j*64+d] = sum_i Wk[i*64+d] * Wq[i*64+j]
    for (int e = tid; e < DD * DD; e += 256) {
        int j = e >> 6, d = e & 63;
        float acc = 0.f;
        #pragma unroll 8
        for (int i = 0; i < DD; i++) acc += Wk[i * DD + d] * Wq[i * DD + j];
        g_M2t[e] = acc;
    }
    if (tid < DD) {
        float a = 0.f, u = 0.f;
        #pragma unroll 8
        for (int i = 0; i < DD; i++) {
            a += Wk[i * DD + tid] * bq[i];
            u += Wq[i * DD + tid] * bk[i];
        }
        g_mb[tid] = a;
        g_u[tid]  = u;
    }
    if (tid == DD) {
        float t = 0.f;
        for (int i = 0; i < DD; i++) t += bq[i] * bk[i];
        g_t = t;
    }
    // T[i*64+d] = sum_j Wp[i,j]*Wv[j,d]
    for (int e = tid; e < DD * DD; e += 256) {
        int i = e >> 6, d = e & 63;
        float acc = 0.f;
        #pragma unroll 8
        for (int j = 0; j < DD; j++) acc += Wp[i * DD + j] * Wv[j * DD + d];
        T[e] = acc;
    }
    __syncthreads();
    // F[k*64+d] = sum_i Wc[k,i]*T[i,d]
    if (tid < 2 * DD) {
        int k = tid >> 6, d = tid & 63;
        float acc = 0.f;
        #pragma unroll 8
        for (int i = 0; i < DD; i++) acc += Wc[k * DD + i] * T[i * DD + d];
        g_F[tid] = acc;
    }
    // f0[k] = Wc[k] . (Wp bv + bp) + bc[k]
    if (tid >= 128 && tid < 130) {
        int k = tid - 128;
        float acc = bc[k];
        for (int i = 0; i < DD; i++) {
            float tmp = bp[i];
            for (int j = 0; j < DD; j++) tmp += Wp[i * DD + j] * bv[j];
            acc += Wc[k * DD + i] * tmp;
        }
        g_f0[k] = acc;
    }
}

__global__ __launch_bounds__(256) void crec_main(
    const int*   __restrict__ hist, const int* __restrict__ cand,
    const int*   __restrict__ label, const float* __restrict__ emb)
{
    extern __shared__ float h[];  // [DD][SROW] transposed history tile
    __shared__ int   hidx[SS];
    __shared__ float csh[DD], msh[DD], haggsh[DD];
    __shared__ float logits[SS];
    __shared__ float red[256];
    __shared__ float cconst_sh;

    const int b   = blockIdx.x;
    const int tid = threadIdx.x;

    if (tid < SS) hidx[tid] = hist[b * SS + tid];
    if (tid < DD) {
        int ci = cand[b];
        csh[tid] = (ci != 0) ? emb[ci * DD + tid] : 0.0f;  // padding_idx=0
    }
    __syncthreads();

    // m[d] = M2t^T csh + mb[d]   (coalesced over d)
    if (tid < DD) {
        float acc = g_mb[tid];
        #pragma unroll 16
        for (int j = 0; j < DD; j++) acc += g_M2t[j * DD + tid] * csh[j];
        msh[tid] = acc;
    }
    if (tid == DD) {  // cconst = c.u + t  (= q . bk)
        float acc = g_t;
        for (int j = 0; j < DD; j++) acc += csh[j] * g_u[j];
        cconst_sh = acc;
    }

    // Gather history embeddings -> transposed smem tile (float4 global loads)
    const float4* emb4 = (const float4*)emb;
    for (int t = tid; t < SS * 16; t += 256) {
        int s = t >> 4, q = t & 15;
        int idx = hidx[s];
        float4 v = make_float4(0.f, 0.f, 0.f, 0.f);
        if (idx != 0) v = emb4[idx * 16 + q];
        int d0 = q * 4;
        h[(d0 + 0) * SROW + s] = v.x;
        h[(d0 + 1) * SROW + s] = v.y;
        h[(d0 + 2) * SROW + s] = v.z;
        h[(d0 + 3) * SROW + s] = v.w;
    }
    __syncthreads();

    // logits[s] = h[s].m + cconst ; multiplicative NEG mask for hist==0
    float lg = -INFINITY;
    if (tid < SS) {
        float acc = cconst_sh;
        #pragma unroll 16
        for (int d = 0; d < DD; d++) acc += h[d * SROW + tid] * msh[d];
        if (hidx[tid] == 0) acc *= NEGV;
        logits[tid] = acc;
        lg = acc;
    }

    // block max
    red[tid] = lg;
    __syncthreads();
    #pragma unroll
    for (int off = 128; off >= 1; off >>= 1) {
        if (tid < off) red[tid] = fmaxf(red[tid], red[tid + off]);
        __syncthreads();
    }
    const float mx = red[0];
    __syncthreads();

    // exp + sum
    float ex = 0.f;
    if (tid < SS) {
        ex = expf(logits[tid] - mx);
        logits[tid] = ex;       // logits now holds unnormalized scores
    }
    red[tid] = ex;
    __syncthreads();
    #pragma unroll
    for (int off = 128; off >= 1; off >>= 1) {
        if (tid < off) red[tid] += red[tid + off];
        __syncthreads();
    }
    const float den = red[0];
    __syncthreads();

    // hagg[d] = (1/den) * sum_s score[s] * h[d][s]   (stride 201 -> conflict-free)
    if (tid < DD) {
        float acc = 0.f;
        #pragma unroll 8
        for (int s = 0; s < SS; s++) acc += logits[s] * h[tid * SROW + s];
        haggsh[tid] = acc / den;
    }
    __syncthreads();

    // o = F hagg + f0 ; loss_b = logsumexp(o) - o[label]
    if (tid == 0) {
        float o0 = g_f0[0], o1 = g_f0[1];
        #pragma unroll 8
        for (int d = 0; d < DD; d++) {
            float hv = haggsh[d];
            o0 += g_F[d] * hv;
            o1 += g_F[DD + d] * hv;
        }
        int   lab = label[b];
        float mo  = fmaxf(o0, o1);
        float lse = mo + logf(expf(o0 - mo) + expf(o1 - mo));
        g_loss[b] = lse - (lab ? o1 : o0);
    }
}

__global__ __launch_bounds__(256) void crec_reduce(float* __restrict__ out)
{
    __shared__ float red[256];
    const int tid = threadIdx.x;
    float acc = 0.f;
    for (int i = tid; i < BB; i += 256) acc += g_loss[i];
    red[tid] = acc;
    __syncthreads();
    #pragma unroll
    for (int off = 128; off >= 1; off >>= 1) {
        if (tid < off) red[tid] += red[tid + off];
        __syncthreads();
    }
    if (tid == 0) out[0] = red[0] / (float)BB;
}

extern "C" void kernel_launch(void* const* d_in, const int* in_sizes, int n_in,
                              void* d_out, int out_size)
{
    const int*   hist  = (const int*)  d_in[0];
    const int*   cand  = (const int*)  d_in[1];
    const int*   label = (const int*)  d_in[2];
    const float* emb   = (const float*)d_in[3];
    const float* Wq    = (const float*)d_in[4];
    const float* bq    = (const float*)d_in[5];
    const float* Wk    = (const float*)d_in[6];
    const float* bk    = (const float*)d_in[7];
    const float* Wv    = (const float*)d_in[8];
    const float* bv    = (const float*)d_in[9];
    const float* Wp    = (const float*)d_in[10];
    const float* bp    = (const float*)d_in[11];
    const float* Wc    = (const float*)d_in[12];
    const float* bc    = (const float*)d_in[13];

    const int smem = DD * SROW * sizeof(float);  // 51456 B
    cudaFuncSetAttribute(crec_main, cudaFuncAttributeMaxDynamicSharedMemorySize, smem);

    crec_prep<<<1, 256>>>(Wq, bq, Wk, bk, Wv, bv, Wp, bp, Wc, bc);
    crec_main<<<BB, 256, smem>>>(hist, cand, label, emb);
    crec_reduce<<<1, 256>>>((float*)d_out);
}

// round 2
// speedup vs baseline: 2.2613x; 2.2613x over previous
#include <cuda_runtime.h>
#include <cuda_fp16.h>
#include <math.h>

#define BB    8192
#define SS    200
#define DD    64
#define SROWH 202              // halves per row = 101 words (odd) -> conflict-free
#define NEGV  (-4294967296.0f) // -2^32

// Precomputed fused parameters
__device__ float g_M2t[DD * DD];  // M2t[j*64+d] = sum_i Wk[i,d]*Wq[i,j]
__device__ float g_mb[DD];        // Wk^T bq
__device__ float g_u[DD];         // Wq^T bk
__device__ float g_t;             // bq.bk
__device__ float g_F[2 * DD];     // Wc @ Wp @ Wv
__device__ float g_f0[2];         // Wc(Wp bv + bp) + bc
__device__ float g_loss[BB];

// ---------------- prep: grid = 17 blocks ----------------
__global__ __launch_bounds__(256) void crec_prep(
    const float* __restrict__ Wq, const float* __restrict__ bq,
    const float* __restrict__ Wk, const float* __restrict__ bk,
    const float* __restrict__ Wv, const float* __restrict__ bv,
    const float* __restrict__ Wp, const float* __restrict__ bp,
    const float* __restrict__ Wc, const float* __restrict__ bc)
{
    const int tid = threadIdx.x;
    const int blk = blockIdx.x;

    if (blk < 16) {
        // M2t[j*64+d] = sum_i Wk[i*64+d] * Wq[i*64+j]
        const int e = blk * 256 + tid;
        const int j = e >> 6, d = e & 63;
        float acc = 0.f;
        #pragma unroll 8
        for (int i = 0; i < DD; i++) acc += Wk[i * DD + d] * Wq[i * DD + j];
        g_M2t[e] = acc;
        return;
    }

    // block 16: everything else (all tiny)
    __shared__ float Gsh[2 * DD];
    __shared__ float wsh[DD];

    if (tid < DD) {
        float a = 0.f, u = 0.f;
        #pragma unroll 8
        for (int i = 0; i < DD; i++) {
            a += Wk[i * DD + tid] * bq[i];
            u += Wq[i * DD + tid] * bk[i];
        }
        g_mb[tid] = a;
        g_u[tid]  = u;
    }
    if (tid == DD) {
        float t = 0.f;
        for (int i = 0; i < DD; i++) t += bq[i] * bk[i];
        g_t = t;
    }
    if (tid < 2 * DD) {  // G[k,j] = sum_i Wc[k,i]*Wp[i,j]
        const int k = tid >> 6, j = tid & 63;
        float acc = 0.f;
        #pragma unroll 8
        for (int i = 0; i < DD; i++) acc += Wc[k * DD + i] * Wp[i * DD + j];
        Gsh[tid] = acc;
    }
    if (tid >= 128 && tid < 192) {  // w[i] = Wp[i,:].bv
        const int i = tid - 128;
        float acc = 0.f;
        #pragma unroll 8
        for (int j = 0; j < DD; j++) acc += Wp[i * DD + j] * bv[j];
        wsh[i] = acc;
    }
    __syncthreads();
    if (tid < 2 * DD) {  // F[k,d] = sum_j G[k,j]*Wv[j,d]
        const int k = tid >> 6, d = tid & 63;
        float acc = 0.f;
        #pragma unroll 8
        for (int j = 0; j < DD; j++) acc += Gsh[k * DD + j] * Wv[j * DD + d];
        g_F[tid] = acc;
    }
    if (tid >= 128 && tid < 130) {  // f0[k] = Wc[k,:].(w+bp) + bc[k]
        const int k = tid - 128;
        float acc = bc[k];
        for (int i = 0; i < DD; i++) acc += Wc[k * DD + i] * (wsh[i] + bp[i]);
        g_f0[k] = acc;
    }
}

// ---------------- main: grid = 8192 blocks ----------------
__global__ __launch_bounds__(256) void crec_main(
    const int*   __restrict__ hist, const int* __restrict__ cand,
    const int*   __restrict__ label, const float* __restrict__ emb)
{
    __shared__ __align__(8) __half h[DD * SROWH];  // 25856 B, transposed tile
    __shared__ int   hidx[SS];
    __shared__ float csh[DD], msh[DD], haggsh[DD];
    __shared__ float logits[SS];
    __shared__ float red[256];
    __shared__ float redm[8], reds[8];
    __shared__ float cconst_sh;

    const int b    = blockIdx.x;
    const int tid  = threadIdx.x;
    const int lane = tid & 31;

    // ---- phase A: indices + candidate embedding ----
    if (tid < SS) hidx[tid] = hist[b * SS + tid];
    if (tid < DD) {
        const int ci = cand[b];
        csh[tid] = (ci != 0) ? emb[ci * DD + tid] : 0.0f;  // padding_idx=0
    }
    __syncthreads();

    // ---- phase B: threads 0-63 compute m; 64-255 gather history ----
    if (tid < DD) {
        float acc = g_mb[tid];
        #pragma unroll 16
        for (int j = 0; j < DD; j++) acc += g_M2t[j * DD + tid] * csh[j];
        msh[tid] = acc;
    } else {
        if (tid == 255) {  // cconst = c.u + bq.bk  (= q.bk)
            float acc = g_t;
            #pragma unroll 8
            for (int j = 0; j < DD; j++) acc += csh[j] * g_u[j];
            cconst_sh = acc;
        }
        // gather: s-pairs x 16 q-chunks; 1600 units over 192 threads
        const float4* __restrict__ emb4 = (const float4*)emb;
        for (int t = tid - 64; t < (SS / 2) * 16; t += 192) {
            const int sp = t >> 4, q = t & 15;
            const int s0 = 2 * sp;
            const int i0 = hidx[s0], i1 = hidx[s0 + 1];
            float4 v0 = make_float4(0.f, 0.f, 0.f, 0.f);
            float4 v1 = make_float4(0.f, 0.f, 0.f, 0.f);
            if (i0 != 0) v0 = emb4[i0 * 16 + q];
            if (i1 != 0) v1 = emb4[i1 * 16 + q];
            const int d0 = 4 * q;
            *(half2*)&h[(d0 + 0) * SROWH + s0] = __floats2half2_rn(v0.x, v1.x);
            *(half2*)&h[(d0 + 1) * SROWH + s0] = __floats2half2_rn(v0.y, v1.y);
            *(half2*)&h[(d0 + 2) * SROWH + s0] = __floats2half2_rn(v0.z, v1.z);
            *(half2*)&h[(d0 + 3) * SROWH + s0] = __floats2half2_rn(v0.w, v1.w);
        }
    }
    __syncthreads();

    // ---- phase C: logits + softmax ----
    float lg = -INFINITY;
    if (tid < SS) {
        float acc = cconst_sh;
        #pragma unroll 16
        for (int d = 0; d < DD; d++)
            acc += __half2float(h[d * SROWH + tid]) * msh[d];
        if (hidx[tid] == 0) acc *= NEGV;  // reference's multiplicative mask
        lg = acc;
    }
    // warp-shuffle max, then 8-value broadcast
    float r = lg;
    #pragma unroll
    for (int off = 16; off >= 1; off >>= 1)
        r = fmaxf(r, __shfl_xor_sync(0xffffffffu, r, off));
    if (lane == 0) redm[tid >> 5] = r;
    __syncthreads();
    float mx = redm[0];
    #pragma unroll
    for (int w = 1; w < 8; w++) mx = fmaxf(mx, redm[w]);

    float ex = 0.f;
    if (tid < SS) {
        ex = __expf(lg - mx);
        logits[tid] = ex;  // unnormalized score
    }
    r = ex;
    #pragma unroll
    for (int off = 16; off >= 1; off >>= 1)
        r += __shfl_xor_sync(0xffffffffu, r, off);
    if (lane == 0) reds[tid >> 5] = r;
    __syncthreads();  // also covers logits[] stores
    float den = reds[0];
    #pragma unroll
    for (int w = 1; w < 8; w++) den += reds[w];

    // ---- phase D: hagg[d] = sum_s score*h / den (4 partials x 64 d) ----
    {
        const int d = tid & 63, c = tid >> 6;
        const int sp0 = c * 25;  // 25 s-pairs per chunk (50 s)
        float acc = 0.f;
        #pragma unroll 5
        for (int sp = sp0; sp < sp0 + 25; sp++) {
            const half2 hv = *(const half2*)&h[d * SROWH + 2 * sp];
            const float2 f = __half22float2(hv);
            acc += logits[2 * sp] * f.x + logits[2 * sp + 1] * f.y;
        }
        red[tid] = acc;
    }
    __syncthreads();
    if (tid < DD) {
        haggsh[tid] = (red[tid] + red[64 + tid] + red[128 + tid] + red[192 + tid]) / den;
    }
    __syncthreads();

    // ---- phase E: head + per-row loss (one warp) ----
    if (tid < 32) {
        const float hl = haggsh[tid], hh = haggsh[tid + 32];
        float a0 = g_F[tid]      * hl + g_F[tid + 32] * hh;
        float a1 = g_F[64 + tid] * hl + g_F[96 + tid] * hh;
        #pragma unroll
        for (int off = 16; off >= 1; off >>= 1) {
            a0 += __shfl_xor_sync(0xffffffffu, a0, off);
            a1 += __shfl_xor_sync(0xffffffffu, a1, off);
        }
        if (tid == 0) {
            const float o0 = a0 + g_f0[0];
            const float o1 = a1 + g_f0[1];
            const int   lab = label[b];
            const float mo  = fmaxf(o0, o1);
            const float lse = mo + logf(__expf(o0 - mo) + __expf(o1 - mo));
            g_loss[b] = lse - (lab ? o1 : o0);
        }
    }
}

__global__ __launch_bounds__(256) void crec_reduce(float* __restrict__ out)
{
    __shared__ float red[256];
    const int tid = threadIdx.x;
    float acc = 0.f;
    for (int i = tid; i < BB; i += 256) acc += g_loss[i];
    red[tid] = acc;
    __syncthreads();
    #pragma unroll
    for (int off = 128; off >= 1; off >>= 1) {
        if (tid < off) red[tid] += red[tid + off];
        __syncthreads();
    }
    if (tid == 0) out[0] = red[0] / (float)BB;
}

extern "C" void kernel_launch(void* const* d_in, const int* in_sizes, int n_in,
                              void* d_out, int out_size)
{
    const int*   hist  = (const int*)  d_in[0];
    const int*   cand  = (const int*)  d_in[1];
    const int*   label = (const int*)  d_in[2];
    const float* emb   = (const float*)d_in[3];
    const float* Wq    = (const float*)d_in[4];
    const float* bq    = (const float*)d_in[5];
    const float* Wk    = (const float*)d_in[6];
    const float* bk    = (const float*)d_in[7];
    const float* Wv    = (const float*)d_in[8];
    const float* bv    = (const float*)d_in[9];
    const float* Wp    = (const float*)d_in[10];
    const float* bp    = (const float*)d_in[11];
    const float* Wc    = (const float*)d_in[12];
    const float* bc    = (const float*)d_in[13];

    crec_prep<<<17, 256>>>(Wq, bq, Wk, bk, Wv, bv, Wp, bp, Wc, bc);
    crec_main<<<BB, 256>>>(hist, cand, label, emb);
    crec_reduce<<<1, 256>>>((float*)d_out);
}

// round 3
// speedup vs baseline: 2.3007x; 1.0175x over previous
#include <cuda_runtime.h>
#include <cuda_fp16.h>
#include <math.h>

#define BB    8192
#define SS    200
#define DD    64
#define SROWH 202              // halves per row = 101 words (odd) -> conflict-free
#define NEGV  (-4294967296.0f) // -2^32
#define QROWS 32
#define QGRID (BB / QROWS)     // 256

// Per-row precomputed attention query data + fused head
__device__ float    g_mrow[BB * DD]; // m[b][d] : logits[b][s] = h[s].m[b] + cc[b]
__device__ float    g_mc[BB];        // cc[b] = q.bk
__device__ float    g_F[2 * DD];     // Wc @ Wp @ Wv
__device__ float    g_f0[2];         // Wc(Wp bv + bp) + bc
__device__ float    g_loss[BB];
__device__ unsigned g_cnt;

// ---------------- qprep: per-row q-side matvecs + fused head consts ----------------
extern __shared__ float dynsm[];
__global__ __launch_bounds__(256) void crec_qprep(
    const int*   __restrict__ cand, const float* __restrict__ emb,
    const float* __restrict__ Wq, const float* __restrict__ bq,
    const float* __restrict__ Wk, const float* __restrict__ bk,
    const float* __restrict__ Wv, const float* __restrict__ bv,
    const float* __restrict__ Wp, const float* __restrict__ bp,
    const float* __restrict__ Wc, const float* __restrict__ bc)
{
    float* WqT  = dynsm;          // [64*65]  WqT[j*65+d] = Wq[d][j]
    float* Wks  = dynsm + 4160;   // [64*64]  row-major copy of Wk
    float* csh  = dynsm + 8256;   // [4][64][8]  c[j] for 8 rows per group
    float* qsh  = dynsm + 10304;  // [4][64][8]  q[i] for 8 rows per group
    float* bqs  = dynsm + 12352;  // [64]
    float* bks  = dynsm + 12416;  // [64]
    float* cred = dynsm + 12480;  // [4][2][8]
    int*   cish = (int*)(dynsm + 12544); // [32]

    const int tid = threadIdx.x;
    const int d   = tid & 63, g = tid >> 6;
    const int rowbase = blockIdx.x * QROWS + g * 8;

    // load weights (coalesced global; conflict-free smem stores)
    for (int x = tid; x < 4096; x += 256) {
        const int r = x >> 6, c = x & 63;
        WqT[c * 65 + r] = Wq[x];
        Wks[x]          = Wk[x];
    }
    if (tid < 64) { bqs[tid] = bq[tid]; bks[tid] = bk[tid]; }
    if (tid >= 64 && tid < 64 + QROWS) cish[tid - 64] = cand[blockIdx.x * QROWS + (tid - 64)];
    __syncthreads();

    // candidate embeddings -> csh[g][j][r]
    #pragma unroll
    for (int r = 0; r < 8; r++) {
        const int ci = cish[g * 8 + r];
        csh[g * 512 + d * 8 + r] = (ci != 0) ? emb[ci * DD + d] : 0.f; // padding_idx=0
    }
    __syncthreads();

    // stage 1: q_r[d] = bq[d] + sum_j Wq[d][j] * c_r[j]
    float acc[8];
    #pragma unroll
    for (int r = 0; r < 8; r++) acc[r] = bqs[d];
    #pragma unroll 4
    for (int j = 0; j < 64; j++) {
        const float  w  = WqT[j * 65 + d];
        const float4 cA = *(const float4*)&csh[g * 512 + j * 8];
        const float4 cB = *(const float4*)&csh[g * 512 + j * 8 + 4];
        acc[0] += w * cA.x; acc[1] += w * cA.y; acc[2] += w * cA.z; acc[3] += w * cA.w;
        acc[4] += w * cB.x; acc[5] += w * cB.y; acc[6] += w * cB.z; acc[7] += w * cB.w;
    }
    *(float4*)&qsh[g * 512 + d * 8]     = make_float4(acc[0], acc[1], acc[2], acc[3]);
    *(float4*)&qsh[g * 512 + d * 8 + 4] = make_float4(acc[4], acc[5], acc[6], acc[7]);
    {   // cconst_r = bk . q_r  (group = 2 warps)
        const float bkd = bks[d];
        #pragma unroll
        for (int r = 0; r < 8; r++) {
            float p = bkd * acc[r];
            #pragma unroll
            for (int off = 16; off >= 1; off >>= 1) p += __shfl_xor_sync(0xffffffffu, p, off);
            if ((d & 31) == 0) cred[g * 16 + (d >> 5) * 8 + r] = p;
        }
    }
    __syncthreads();
    if (d < 8) g_mc[rowbase + d] = cred[g * 16 + d] + cred[g * 16 + 8 + d];

    // stage 2: m_r[d] = sum_i Wk[i][d] * q_r[i]
    float m[8];
    #pragma unroll
    for (int r = 0; r < 8; r++) m[r] = 0.f;
    #pragma unroll 4
    for (int i = 0; i < 64; i++) {
        const float  w  = Wks[i * 64 + d];
        const float4 qA = *(const float4*)&qsh[g * 512 + i * 8];
        const float4 qB = *(const float4*)&qsh[g * 512 + i * 8 + 4];
        m[0] += w * qA.x; m[1] += w * qA.y; m[2] += w * qA.z; m[3] += w * qA.w;
        m[4] += w * qB.x; m[5] += w * qB.y; m[6] += w * qB.z; m[7] += w * qB.w;
    }
    #pragma unroll
    for (int r = 0; r < 8; r++) g_mrow[(rowbase + r) * DD + d] = m[r];

    // block 0: fused head consts F = Wc@Wp@Wv, f0; reset completion counter
    if (blockIdx.x == 0) {
        __syncthreads();
        float* Gsh = csh;         // reuse (reads of csh are done)
        float* wsh = csh + 128;
        if (tid < 128) {          // G[k,j] = Wc[k,:].Wp[:,j]
            const int k = tid >> 6, j = tid & 63;
            float a = 0.f;
            #pragma unroll 8
            for (int i = 0; i < DD; i++) a += Wc[k * DD + i] * Wp[i * DD + j];
            Gsh[tid] = a;
        }
        if (tid >= 128 && tid < 192) { // w[i] = Wp[i,:].bv
            const int i = tid - 128;
            float a = 0.f;
            #pragma unroll 8
            for (int j = 0; j < DD; j++) a += Wp[i * DD + j] * bv[j];
            wsh[i] = a;
        }
        __syncthreads();
        if (tid < 128) {          // F[k,d] = G[k,:].Wv[:,d]
            const int k = tid >> 6, dd = tid & 63;
            float a = 0.f;
            #pragma unroll 8
            for (int j = 0; j < DD; j++) a += Gsh[k * DD + j] * Wv[j * DD + dd];
            g_F[tid] = a;
        }
        if (tid == 192 || tid == 193) {
            const int k = tid - 192;
            float a = bc[k];
            for (int i = 0; i < DD; i++) a += Wc[k * DD + i] * (wsh[i] + bp[i]);
            g_f0[k] = a;
        }
        if (tid == 0) g_cnt = 0u;
    }
}

// ---------------- main: gather + attention + loss (+ last-block reduce) ----------------
__global__ __launch_bounds__(256) void crec_main(
    const int*   __restrict__ hist, const int* __restrict__ label,
    const float* __restrict__ emb,  float* __restrict__ out)
{
    __shared__ __align__(8)  __half h[DD * SROWH];   // 25856 B transposed fp16 tile
    __shared__ __align__(16) float  pool[256];       // hidx (phases A-C) then red (phase D+)
    __shared__ float logits[SS];
    __shared__ float msh[DD], haggsh[DD];
    __shared__ float redm[8], reds[8];
    __shared__ float ccsh;
    __shared__ int   flag_sh;

    int*   hidx = (int*)pool;
    float* red  = pool;

    const int b    = blockIdx.x;
    const int tid  = threadIdx.x;
    const int lane = tid & 31;

    // ---- phase A ----
    if (tid < SS) hidx[tid] = hist[b * SS + tid];
    if (tid < DD) msh[tid] = g_mrow[b * DD + tid];
    if (tid == 254) ccsh = g_mc[b];
    __syncthreads();

    // ---- phase B: gather, all 256 threads ----
    const float4* __restrict__ emb4 = (const float4*)emb;
    for (int t = tid; t < (SS / 2) * 16; t += 256) {
        const int sp = t >> 4, q = t & 15;
        const int s0 = 2 * sp;
        const int i0 = hidx[s0], i1 = hidx[s0 + 1];
        float4 v0 = make_float4(0.f, 0.f, 0.f, 0.f);
        float4 v1 = make_float4(0.f, 0.f, 0.f, 0.f);
        if (i0 != 0) v0 = emb4[i0 * 16 + q];
        if (i1 != 0) v1 = emb4[i1 * 16 + q];
        const int d0 = 4 * q;
        *(half2*)&h[(d0 + 0) * SROWH + s0] = __floats2half2_rn(v0.x, v1.x);
        *(half2*)&h[(d0 + 1) * SROWH + s0] = __floats2half2_rn(v0.y, v1.y);
        *(half2*)&h[(d0 + 2) * SROWH + s0] = __floats2half2_rn(v0.z, v1.z);
        *(half2*)&h[(d0 + 3) * SROWH + s0] = __floats2half2_rn(v0.w, v1.w);
    }
    __syncthreads();

    // ---- phase C: logits + softmax ----
    float lg = -INFINITY;
    if (tid < SS) {
        float acc = ccsh;
        #pragma unroll 16
        for (int d = 0; d < DD; d++)
            acc += __half2float(h[d * SROWH + tid]) * msh[d];
        if (hidx[tid] == 0) acc *= NEGV;  // reference's multiplicative mask
        lg = acc;
    }
    float r = lg;
    #pragma unroll
    for (int off = 16; off >= 1; off >>= 1)
        r = fmaxf(r, __shfl_xor_sync(0xffffffffu, r, off));
    if (lane == 0) redm[tid >> 5] = r;
    __syncthreads();
    float mx = redm[0];
    #pragma unroll
    for (int w = 1; w < 8; w++) mx = fmaxf(mx, redm[w]);

    float ex = 0.f;
    if (tid < SS) {
        ex = __expf(lg - mx);
        logits[tid] = ex;
    }
    r = ex;
    #pragma unroll
    for (int off = 16; off >= 1; off >>= 1)
        r += __shfl_xor_sync(0xffffffffu, r, off);
    if (lane == 0) reds[tid >> 5] = r;
    __syncthreads();   // covers logits stores; after this hidx region becomes red
    float den = reds[0];
    #pragma unroll
    for (int w = 1; w < 8; w++) den += reds[w];

    // ---- phase D: hagg[d] = sum_s score*h / den ----
    {
        const int d = tid & 63, c = tid >> 6;
        const int sp0 = c * 25;
        float acc = 0.f;
        #pragma unroll 5
        for (int sp = sp0; sp < sp0 + 25; sp++) {
            const half2  hv = *(const half2*)&h[d * SROWH + 2 * sp];
            const float2 f  = __half22float2(hv);
            acc += logits[2 * sp] * f.x + logits[2 * sp + 1] * f.y;
        }
        red[tid] = acc;
    }
    __syncthreads();
    if (tid < DD)
        haggsh[tid] = (red[tid] + red[64 + tid] + red[128 + tid] + red[192 + tid]) / den;
    __syncthreads();

    // ---- phase E: head + per-row loss ----
    if (tid < 32) {
        const float hl = haggsh[tid], hh = haggsh[tid + 32];
        float a0 = g_F[tid]      * hl + g_F[tid + 32] * hh;
        float a1 = g_F[64 + tid] * hl + g_F[96 + tid] * hh;
        #pragma unroll
        for (int off = 16; off >= 1; off >>= 1) {
            a0 += __shfl_xor_sync(0xffffffffu, a0, off);
            a1 += __shfl_xor_sync(0xffffffffu, a1, off);
        }
        if (tid == 0) {
            const float o0  = a0 + g_f0[0];
            const float o1  = a1 + g_f0[1];
            const int   lab = label[b];
            const float mo  = fmaxf(o0, o1);
            const float lse = mo + logf(__expf(o0 - mo) + __expf(o1 - mo));
            g_loss[b] = lse - (lab ? o1 : o0);
        }
    }

    // ---- tail: last block reduces (deterministic fixed-order sum) ----
    if (tid == 0) {
        __threadfence();
        const unsigned p = atomicAdd(&g_cnt, 1u);
        flag_sh = (p == BB - 1u) ? 1 : 0;
    }
    __syncthreads();
    if (flag_sh) {
        float acc = 0.f;
        for (int i = tid; i < BB; i += 256) acc += __ldcg(&g_loss[i]);
        red[tid] = acc;
        __syncthreads();
        #pragma unroll
        for (int off = 128; off >= 1; off >>= 1) {
            if (tid < off) red[tid] += red[tid + off];
            __syncthreads();
        }
        if (tid == 0) out[0] = red[0] / (float)BB;
    }
}

extern "C" void kernel_launch(void* const* d_in, const int* in_sizes, int n_in,
                              void* d_out, int out_size)
{
    const int*   hist  = (const int*)  d_in[0];
    const int*   cand  = (const int*)  d_in[1];
    const int*   label = (const int*)  d_in[2];
    const float* emb   = (const float*)d_in[3];
    const float* Wq    = (const float*)d_in[4];
    const float* bq    = (const float*)d_in[5];
    const float* Wk    = (const float*)d_in[6];
    const float* bk    = (const float*)d_in[7];
    const float* Wv    = (const float*)d_in[8];
    const float* bv    = (const float*)d_in[9];
    const float* Wp    = (const float*)d_in[10];
    const float* bp    = (const float*)d_in[11];
    const float* Wc    = (const float*)d_in[12];
    const float* bc    = (const float*)d_in[13];

    const int qsmem = 12576 * (int)sizeof(float);  // 50304 B
    cudaFuncSetAttribute(crec_qprep, cudaFuncAttributeMaxDynamicSharedMemorySize, qsmem);

    crec_qprep<<<QGRID, 256, qsmem>>>(cand, emb, Wq, bq, Wk, bk, Wv, bv, Wp, bp, Wc, bc);
    crec_main<<<BB, 256>>>(hist, label, emb, (float*)d_out);
}

// round 4
// speedup vs baseline: 2.5969x; 1.1287x over previous
#include <cuda_runtime.h>
#include <cuda_fp16.h>
#include <math.h>

#define BB    8192
#define SS    200
#define SP    100               // s-pairs
#define DD    64
#define TSTR  68                // tile row stride in half2 words (4-aligned, conflict-free)
#define NEGV  (-4294967296.0f)  // -2^32
#define QROWS 64
#define QGRID (BB / QROWS)      // 128

// Per-row precomputed attention query data + fused head
__device__ float    g_mrow[BB * DD]; // m[b][d] : logits[b][s] = h[s].m[b] + cc[b]
__device__ float    g_mc[BB];        // cc[b] = q.bk
__device__ float    g_F[2 * DD];     // Wc @ Wp @ Wv
__device__ float    g_f0[2];         // Wc(Wp bv + bp) + bc
__device__ float    g_loss[BB];
__device__ unsigned g_cnt;

// ---------------- qprep: 128 blocks x 512 threads, 64 rows/block ----------------
extern __shared__ float dynsm[];
__global__ __launch_bounds__(512) void crec_qprep(
    const int*   __restrict__ cand, const float* __restrict__ emb,
    const float* __restrict__ Wq, const float* __restrict__ bq,
    const float* __restrict__ Wk, const float* __restrict__ bk,
    const float* __restrict__ Wv, const float* __restrict__ bv,
    const float* __restrict__ Wp, const float* __restrict__ bp,
    const float* __restrict__ Wc, const float* __restrict__ bc)
{
    float* WqT  = dynsm;           // [64*65]  WqT[j*65+d] = Wq[d][j]
    float* Wks  = dynsm + 4160;    // [64*64]
    float* csh  = dynsm + 8256;    // [8][64][8]
    float* qsh  = dynsm + 12352;   // [8][64][8]
    float* bqs  = dynsm + 16448;   // [64]
    float* bks  = dynsm + 16512;   // [64]
    float* cred = dynsm + 16576;   // [8][2][8]
    int*   cish = (int*)(dynsm + 16704); // [64]

    const int tid = threadIdx.x;
    const int d   = tid & 63, g = tid >> 6;          // 8 groups of 64 threads (2 warps)
    const int rowbase = blockIdx.x * QROWS + g * 8;

    for (int x = tid; x < 4096; x += 512) {
        const int r = x >> 6, c = x & 63;
        WqT[c * 65 + r] = Wq[x];
        Wks[x]          = Wk[x];
    }
    if (tid < 64) { bqs[tid] = bq[tid]; bks[tid] = bk[tid]; }
    if (tid >= 64 && tid < 64 + QROWS) cish[tid - 64] = cand[blockIdx.x * QROWS + (tid - 64)];
    __syncthreads();

    #pragma unroll
    for (int r = 0; r < 8; r++) {
        const int ci = cish[g * 8 + r];
        csh[g * 512 + d * 8 + r] = (ci != 0) ? emb[ci * DD + d] : 0.f; // padding_idx=0
    }
    __syncthreads();

    // stage 1: q_r[d] = bq[d] + sum_j Wq[d][j] * c_r[j]
    float acc[8];
    #pragma unroll
    for (int r = 0; r < 8; r++) acc[r] = bqs[d];
    #pragma unroll 4
    for (int j = 0; j < 64; j++) {
        const float  w  = WqT[j * 65 + d];
        const float4 cA = *(const float4*)&csh[g * 512 + j * 8];
        const float4 cB = *(const float4*)&csh[g * 512 + j * 8 + 4];
        acc[0] += w * cA.x; acc[1] += w * cA.y; acc[2] += w * cA.z; acc[3] += w * cA.w;
        acc[4] += w * cB.x; acc[5] += w * cB.y; acc[6] += w * cB.z; acc[7] += w * cB.w;
    }
    *(float4*)&qsh[g * 512 + d * 8]     = make_float4(acc[0], acc[1], acc[2], acc[3]);
    *(float4*)&qsh[g * 512 + d * 8 + 4] = make_float4(acc[4], acc[5], acc[6], acc[7]);
    {   // cconst_r = bk . q_r
        const float bkd = bks[d];
        #pragma unroll
        for (int r = 0; r < 8; r++) {
            float p = bkd * acc[r];
            #pragma unroll
            for (int off = 16; off >= 1; off >>= 1) p += __shfl_xor_sync(0xffffffffu, p, off);
            if ((d & 31) == 0) cred[g * 16 + (d >> 5) * 8 + r] = p;
        }
    }
    __syncthreads();
    if (d < 8 && tid < 512) g_mc[rowbase + d] = cred[g * 16 + d] + cred[g * 16 + 8 + d];

    // stage 2: m_r[d] = sum_i Wk[i][d] * q_r[i]
    float m[8];
    #pragma unroll
    for (int r = 0; r < 8; r++) m[r] = 0.f;
    #pragma unroll 4
    for (int i = 0; i < 64; i++) {
        const float  w  = Wks[i * 64 + d];
        const float4 qA = *(const float4*)&qsh[g * 512 + i * 8];
        const float4 qB = *(const float4*)&qsh[g * 512 + i * 8 + 4];
        m[0] += w * qA.x; m[1] += w * qA.y; m[2] += w * qA.z; m[3] += w * qA.w;
        m[4] += w * qB.x; m[5] += w * qB.y; m[6] += w * qB.z; m[7] += w * qB.w;
    }
    #pragma unroll
    for (int r = 0; r < 8; r++) g_mrow[(rowbase + r) * DD + d] = m[r];

    // block 0: fused head consts + counter reset
    if (blockIdx.x == 0) {
        __syncthreads();
        float* Gsh = csh;
        float* wsh = csh + 128;
        if (tid < 128) {          // G[k,j] = Wc[k,:].Wp[:,j]
            const int k = tid >> 6, j = tid & 63;
            float a = 0.f;
            #pragma unroll 8
            for (int i = 0; i < DD; i++) a += Wc[k * DD + i] * Wp[i * DD + j];
            Gsh[tid] = a;
        }
        if (tid >= 128 && tid < 192) { // w[i] = Wp[i,:].bv
            const int i = tid - 128;
            float a = 0.f;
            #pragma unroll 8
            for (int j = 0; j < DD; j++) a += Wp[i * DD + j] * bv[j];
            wsh[i] = a;
        }
        __syncthreads();
        if (tid < 128) {          // F[k,d] = G[k,:].Wv[:,d]
            const int k = tid >> 6, dd = tid & 63;
            float a = 0.f;
            #pragma unroll 8
            for (int j = 0; j < DD; j++) a += Gsh[k * DD + j] * Wv[j * DD + dd];
            g_F[tid] = a;
        }
        if (tid == 192 || tid == 193) {
            const int k = tid - 192;
            float a = bc[k];
            for (int i = 0; i < DD; i++) a += Wc[k * DD + i] * (wsh[i] + bp[i]);
            g_f0[k] = a;
        }
        if (tid == 0) g_cnt = 0u;
    }
}

// ---------------- main: fused gather+logits, softmax, hagg, loss ----------------
__global__ __launch_bounds__(256) void crec_main(
    const int*   __restrict__ hist, const int* __restrict__ label,
    const float* __restrict__ emb,  float* __restrict__ out)
{
    __shared__ __align__(16) __half2 tile[SP * TSTR];  // 27200 B, pair-major: tile[sp*68+d]
    __shared__ __align__(16) float   pool[256];        // hidx (A/B) then red (D+)
    __shared__ __align__(8)  float   logits[SS];
    __shared__ float msh[DD], haggsh[DD];
    __shared__ float redm[8], reds[8];
    __shared__ float ccsh;
    __shared__ int   flag_sh;

    int*   hidx = (int*)pool;
    float* red  = pool;

    const int b    = blockIdx.x;
    const int tid  = threadIdx.x;
    const int lane = tid & 31;

    // ---- phase A ----
    if (tid < SS) hidx[tid] = hist[b * SS + tid];
    if (tid < DD) msh[tid] = g_mrow[b * DD + tid];
    if (tid == 254) ccsh = g_mc[b];
    __syncthreads();

    // ---- phase B: gather + fused logits ----
    // thread = (sp, q): q = tid&15 is loop-invariant; sp strides by 16.
    {
        const int   q  = tid & 15;
        const int   d0 = 4 * q;
        const float4 m4 = *(const float4*)&msh[d0];
        const float cc = ccsh;
        const float4* __restrict__ emb4 = (const float4*)emb;

        for (int sp = tid >> 4; sp < SP; sp += 16) {
            const int  s0 = 2 * sp;
            const int2 ii = *(const int2*)&hidx[s0];       // broadcast within 16-lane group
            float4 v0 = make_float4(0.f, 0.f, 0.f, 0.f);
            float4 v1 = make_float4(0.f, 0.f, 0.f, 0.f);
            if (ii.x != 0) v0 = emb4[ii.x * 16 + q];
            if (ii.y != 0) v1 = emb4[ii.y * 16 + q];

            // pack 4 half2 (dims d0..d0+3, s-pair) -> one STS.128
            half2 h0 = __floats2half2_rn(v0.x, v1.x);
            half2 h1 = __floats2half2_rn(v0.y, v1.y);
            half2 h2 = __floats2half2_rn(v0.z, v1.z);
            half2 h3 = __floats2half2_rn(v0.w, v1.w);
            uint4 pack = make_uint4(*(unsigned*)&h0, *(unsigned*)&h1,
                                    *(unsigned*)&h2, *(unsigned*)&h3);
            *(uint4*)&tile[sp * TSTR + d0] = pack;

            // partial logits for this 4-dim chunk
            float p0 = m4.x * v0.x + m4.y * v0.y + m4.z * v0.z + m4.w * v0.w;
            float p1 = m4.x * v1.x + m4.y * v1.y + m4.z * v1.z + m4.w * v1.w;
            #pragma unroll
            for (int off = 8; off >= 1; off >>= 1) {       // 16-lane group reduce
                p0 += __shfl_xor_sync(0xffffffffu, p0, off);
                p1 += __shfl_xor_sync(0xffffffffu, p1, off);
            }
            if (q == 0) {
                float l0 = p0 + cc; if (ii.x == 0) l0 *= NEGV;  // reference's mult. mask
                float l1 = p1 + cc; if (ii.y == 0) l1 *= NEGV;
                *(float2*)&logits[s0] = make_float2(l0, l1);
            }
        }
    }
    __syncthreads();

    // ---- phase C: softmax over logits ----
    const float lg = (tid < SS) ? logits[tid] : -INFINITY;
    float r = lg;
    #pragma unroll
    for (int off = 16; off >= 1; off >>= 1)
        r = fmaxf(r, __shfl_xor_sync(0xffffffffu, r, off));
    if (lane == 0) redm[tid >> 5] = r;
    __syncthreads();
    float mx = redm[0];
    #pragma unroll
    for (int w = 1; w < 8; w++) mx = fmaxf(mx, redm[w]);

    float ex = 0.f;
    if (tid < SS) {
        ex = __expf(lg - mx);
        logits[tid] = ex;
    }
    r = ex;
    #pragma unroll
    for (int off = 16; off >= 1; off >>= 1)
        r += __shfl_xor_sync(0xffffffffu, r, off);
    if (lane == 0) reds[tid >> 5] = r;
    __syncthreads();   // covers score stores; hidx region becomes red
    float den = reds[0];
    #pragma unroll
    for (int w = 1; w < 8; w++) den += reds[w];

    // ---- phase D: hagg[d] = sum_s score*h / den ----
    {
        const int d = tid & 63, c = tid >> 6;
        const int sp0 = c * 25;
        float acc = 0.f;
        #pragma unroll 5
        for (int sp = sp0; sp < sp0 + 25; sp++) {
            const float2 sc = *(const float2*)&logits[2 * sp];  // warp-broadcast
            const float2 f  = __half22float2(tile[sp * TSTR + d]);
            acc += sc.x * f.x + sc.y * f.y;
        }
        red[tid] = acc;
    }
    __syncthreads();
    if (tid < DD)
        haggsh[tid] = (red[tid] + red[64 + tid] + red[128 + tid] + red[192 + tid]) / den;
    __syncthreads();

    // ---- phase E: head + per-row loss ----
    if (tid < 32) {
        const float hl = haggsh[tid], hh = haggsh[tid + 32];
        float a0 = g_F[tid]      * hl + g_F[tid + 32] * hh;
        float a1 = g_F[64 + tid] * hl + g_F[96 + tid] * hh;
        #pragma unroll
        for (int off = 16; off >= 1; off >>= 1) {
            a0 += __shfl_xor_sync(0xffffffffu, a0, off);
            a1 += __shfl_xor_sync(0xffffffffu, a1, off);
        }
        if (tid == 0) {
            const float o0  = a0 + g_f0[0];
            const float o1  = a1 + g_f0[1];
            const int   lab = label[b];
            const float mo  = fmaxf(o0, o1);
            const float lse = mo + logf(__expf(o0 - mo) + __expf(o1 - mo));
            g_loss[b] = lse - (lab ? o1 : o0);
        }
    }

    // ---- tail: last block reduces (deterministic fixed-order sum) ----
    if (tid == 0) {
        __threadfence();
        const unsigned p = atomicAdd(&g_cnt, 1u);
        flag_sh = (p == BB - 1u) ? 1 : 0;
    }
    __syncthreads();
    if (flag_sh) {
        float acc = 0.f;
        for (int i = tid; i < BB; i += 256) acc += __ldcg(&g_loss[i]);
        red[tid] = acc;
        __syncthreads();
        #pragma unroll
        for (int off = 128; off >= 1; off >>= 1) {
            if (tid < off) red[tid] += red[tid + off];
            __syncthreads();
        }
        if (tid == 0) out[0] = red[0] / (float)BB;
    }
}

extern "C" void kernel_launch(void* const* d_in, const int* in_sizes, int n_in,
                              void* d_out, int out_size)
{
    const int*   hist  = (const int*)  d_in[0];
    const int*   cand  = (const int*)  d_in[1];
    const int*   label = (const int*)  d_in[2];
    const float* emb   = (const float*)d_in[3];
    const float* Wq    = (const float*)d_in[4];
    const float* bq    = (const float*)d_in[5];
    const float* Wk    = (const float*)d_in[6];
    const float* bk    = (const float*)d_in[7];
    const float* Wv    = (const float*)d_in[8];
    const float* bv    = (const float*)d_in[9];
    const float* Wp    = (const float*)d_in[10];
    const float* bp    = (const float*)d_in[11];
    const float* Wc    = (const float*)d_in[12];
    const float* bc    = (const float*)d_in[13];

    const int qsmem = 16768 * (int)sizeof(float);  // 67072 B
    cudaFuncSetAttribute(crec_qprep, cudaFuncAttributeMaxDynamicSharedMemorySize, qsmem);

    crec_qprep<<<QGRID, 512, qsmem>>>(cand, emb, Wq, bq, Wk, bk, Wv, bv, Wp, bp, Wc, bc);
    crec_main<<<BB, 256>>>(hist, label, emb, (float*)d_out);
}

// round 5
// speedup vs baseline: 2.7304x; 1.0514x over previous
#include <cuda_runtime.h>
#include <cuda_fp16.h>
#include <math.h>

#define BB    8192
#define SS    200
#define SP    100               // s-pairs
#define DD    64
#define TSTR  68                // tile row stride in half2 words (4-aligned, conflict-free)
#define NEGV  (-4294967296.0f)  // -2^32
#define QROWS 64
#define QGRID (BB / QROWS)      // 128

// Per-row precomputed attention query data + fused head
__device__ float    g_mrow[BB * DD]; // m[b][d] : logits[b][s] = h[s].m[b] + cc[b]
__device__ float    g_mc[BB];        // cc[b] = q.bk
__device__ float    g_F[2 * DD];     // Wc @ Wp @ Wv
__device__ float    g_f0[2];         // Wc(Wp bv + bp) + bc
__device__ float    g_loss[BB];
__device__ unsigned g_cnt;

// ---------------- qprep: 128 blocks x 512 threads, 64 rows/block ----------------
extern __shared__ float dynsm[];
__global__ __launch_bounds__(512) void crec_qprep(
    const int*   __restrict__ cand, const float* __restrict__ emb,
    const float* __restrict__ Wq, const float* __restrict__ bq,
    const float* __restrict__ Wk, const float* __restrict__ bk,
    const float* __restrict__ Wv, const float* __restrict__ bv,
    const float* __restrict__ Wp, const float* __restrict__ bp,
    const float* __restrict__ Wc, const float* __restrict__ bc)
{
    float* WqT  = dynsm;           // [64*65]  WqT[j*65+d] = Wq[d][j]
    float* Wks  = dynsm + 4160;    // [64*64]
    float* csh  = dynsm + 8256;    // [8][64][8]
    float* qsh  = dynsm + 12352;   // [8][64][8]
    float* bqs  = dynsm + 16448;   // [64]
    float* bks  = dynsm + 16512;   // [64]
    float* cred = dynsm + 16576;   // [8][2][8]
    int*   cish = (int*)(dynsm + 16704); // [64]

    const int tid = threadIdx.x;
    const int d   = tid & 63, g = tid >> 6;          // 8 groups of 64 threads
    const int rowbase = blockIdx.x * QROWS + g * 8;

    for (int x = tid; x < 4096; x += 512) {
        const int r = x >> 6, c = x & 63;
        WqT[c * 65 + r] = Wq[x];
        Wks[x]          = Wk[x];
    }
    if (tid < 64) { bqs[tid] = bq[tid]; bks[tid] = bk[tid]; }
    if (tid >= 64 && tid < 64 + QROWS) cish[tid - 64] = cand[blockIdx.x * QROWS + (tid - 64)];
    __syncthreads();

    #pragma unroll
    for (int r = 0; r < 8; r++) {
        const int ci = cish[g * 8 + r];
        csh[g * 512 + d * 8 + r] = (ci != 0) ? emb[ci * DD + d] : 0.f; // padding_idx=0
    }
    __syncthreads();

    // stage 1: q_r[d] = bq[d] + sum_j Wq[d][j] * c_r[j]
    float acc[8];
    #pragma unroll
    for (int r = 0; r < 8; r++) acc[r] = bqs[d];
    #pragma unroll 4
    for (int j = 0; j < 64; j++) {
        const float  w  = WqT[j * 65 + d];
        const float4 cA = *(const float4*)&csh[g * 512 + j * 8];
        const float4 cB = *(const float4*)&csh[g * 512 + j * 8 + 4];
        acc[0] += w * cA.x; acc[1] += w * cA.y; acc[2] += w * cA.z; acc[3] += w * cA.w;
        acc[4] += w * cB.x; acc[5] += w * cB.y; acc[6] += w * cB.z; acc[7] += w * cB.w;
    }
    *(float4*)&qsh[g * 512 + d * 8]     = make_float4(acc[0], acc[1], acc[2], acc[3]);
    *(float4*)&qsh[g * 512 + d * 8 + 4] = make_float4(acc[4], acc[5], acc[6], acc[7]);
    {   // cconst_r = bk . q_r
        const float bkd = bks[d];
        #pragma unroll
        for (int r = 0; r < 8; r++) {
            float p = bkd * acc[r];
            #pragma unroll
            for (int off = 16; off >= 1; off >>= 1) p += __shfl_xor_sync(0xffffffffu, p, off);
            if ((d & 31) == 0) cred[g * 16 + (d >> 5) * 8 + r] = p;
        }
    }
    __syncthreads();
    if (d < 8) g_mc[rowbase + d] = cred[g * 16 + d] + cred[g * 16 + 8 + d];

    // stage 2: m_r[d] = sum_i Wk[i][d] * q_r[i]
    float m[8];
    #pragma unroll
    for (int r = 0; r < 8; r++) m[r] = 0.f;
    #pragma unroll 4
    for (int i = 0; i < 64; i++) {
        const float  w  = Wks[i * 64 + d];
        const float4 qA = *(const float4*)&qsh[g * 512 + i * 8];
        const float4 qB = *(const float4*)&qsh[g * 512 + i * 8 + 4];
        m[0] += w * qA.x; m[1] += w * qA.y; m[2] += w * qA.z; m[3] += w * qA.w;
        m[4] += w * qB.x; m[5] += w * qB.y; m[6] += w * qB.z; m[7] += w * qB.w;
    }
    #pragma unroll
    for (int r = 0; r < 8; r++) g_mrow[(rowbase + r) * DD + d] = m[r];

    // block 0: fused head consts + counter reset
    if (blockIdx.x == 0) {
        __syncthreads();
        float* Gsh = csh;
        float* wsh = csh + 128;
        if (tid < 128) {          // G[k,j] = Wc[k,:].Wp[:,j]
            const int k = tid >> 6, j = tid & 63;
            float a = 0.f;
            #pragma unroll 8
            for (int i = 0; i < DD; i++) a += Wc[k * DD + i] * Wp[i * DD + j];
            Gsh[tid] = a;
        }
        if (tid >= 128 && tid < 192) { // w[i] = Wp[i,:].bv
            const int i = tid - 128;
            float a = 0.f;
            #pragma unroll 8
            for (int j = 0; j < DD; j++) a += Wp[i * DD + j] * bv[j];
            wsh[i] = a;
        }
        __syncthreads();
        if (tid < 128) {          // F[k,d] = G[k,:].Wv[:,d]
            const int k = tid >> 6, dd = tid & 63;
            float a = 0.f;
            #pragma unroll 8
            for (int j = 0; j < DD; j++) a += Gsh[k * DD + j] * Wv[j * DD + dd];
            g_F[tid] = a;
        }
        if (tid == 192 || tid == 193) {
            const int k = tid - 192;
            float a = bc[k];
            for (int i = 0; i < DD; i++) a += Wc[k * DD + i] * (wsh[i] + bp[i]);
            g_f0[k] = a;
        }
        if (tid == 0) g_cnt = 0u;
    }
}

// ---------------- main: fused gather+logits, softmax, hagg, loss ----------------
__global__ __launch_bounds__(256) void crec_main(
    const int*   __restrict__ hist, const int* __restrict__ label,
    const float* __restrict__ emb,  float* __restrict__ out)
{
    __shared__ __align__(16) __half2 tile[SP * TSTR];  // 27200 B, pair-major
    __shared__ __align__(16) float   pool[256];        // hidx (A/B) then red (D+)
    __shared__ __align__(8)  float   logits[SS];
    __shared__ float msh[DD], haggsh[DD];
    __shared__ float redm[8], reds[8];
    __shared__ float ccsh;
    __shared__ int   flag_sh;

    int*   hidx = (int*)pool;
    float* red  = pool;

    const int b    = blockIdx.x;
    const int tid  = threadIdx.x;
    const int lane = tid & 31;

    // ---- phase A ----
    if (tid < SS) hidx[tid] = hist[b * SS + tid];
    if (tid < DD) msh[tid] = g_mrow[b * DD + tid];
    if (tid == 254) ccsh = g_mc[b];
    __syncthreads();

    // ---- phase B: gather + fused logits; 8 lanes per s-pair, 8 dims per lane ----
    {
        const int    q  = tid & 7;
        const float4 mA = *(const float4*)&msh[4 * q];        // dims 4q..4q+3
        const float4 mB = *(const float4*)&msh[32 + 4 * q];   // dims 32+4q..
        const float  cc = ccsh;
        const float4* __restrict__ emb4 = (const float4*)emb;

        for (int sp = tid >> 3; sp < SP; sp += 32) {
            const int  s0 = 2 * sp;
            const int2 ii = *(const int2*)&hidx[s0];
            float4 a0 = make_float4(0.f,0.f,0.f,0.f), b0 = a0, a1 = a0, b1 = a0;
            if (ii.x != 0) { a0 = emb4[ii.x * 16 + q]; b0 = emb4[ii.x * 16 + 8 + q]; }
            if (ii.y != 0) { a1 = emb4[ii.y * 16 + q]; b1 = emb4[ii.y * 16 + 8 + q]; }

            // pack fp16 tile: two dense 128B regions per s-pair
            half2 hA0 = __floats2half2_rn(a0.x, a1.x);
            half2 hA1 = __floats2half2_rn(a0.y, a1.y);
            half2 hA2 = __floats2half2_rn(a0.z, a1.z);
            half2 hA3 = __floats2half2_rn(a0.w, a1.w);
            half2 hB0 = __floats2half2_rn(b0.x, b1.x);
            half2 hB1 = __floats2half2_rn(b0.y, b1.y);
            half2 hB2 = __floats2half2_rn(b0.z, b1.z);
            half2 hB3 = __floats2half2_rn(b0.w, b1.w);
            *(uint4*)&tile[sp * TSTR + 4 * q] =
                make_uint4(*(unsigned*)&hA0, *(unsigned*)&hA1,
                           *(unsigned*)&hA2, *(unsigned*)&hA3);
            *(uint4*)&tile[sp * TSTR + 32 + 4 * q] =
                make_uint4(*(unsigned*)&hB0, *(unsigned*)&hB1,
                           *(unsigned*)&hB2, *(unsigned*)&hB3);

            // 8-dim partial dots, 8-lane butterfly
            float p0 = mA.x*a0.x + mA.y*a0.y + mA.z*a0.z + mA.w*a0.w
                     + mB.x*b0.x + mB.y*b0.y + mB.z*b0.z + mB.w*b0.w;
            float p1 = mA.x*a1.x + mA.y*a1.y + mA.z*a1.z + mA.w*a1.w
                     + mB.x*b1.x + mB.y*b1.y + mB.z*b1.z + mB.w*b1.w;
            #pragma unroll
            for (int off = 4; off >= 1; off >>= 1) {
                p0 += __shfl_xor_sync(0xffffffffu, p0, off);
                p1 += __shfl_xor_sync(0xffffffffu, p1, off);
            }
            if (q == 0) {
                float l0 = p0 + cc; if (ii.x == 0) l0 *= NEGV;  // mult. mask
                float l1 = p1 + cc; if (ii.y == 0) l1 *= NEGV;
                *(float2*)&logits[s0] = make_float2(l0, l1);
            }
        }
    }
    __syncthreads();

    // ---- phase C: single-round softmax (per-warp max+sum, global combine) ----
    const float lg = (tid < SS) ? logits[tid] : -INFINITY;
    float mw = lg;
    #pragma unroll
    for (int off = 16; off >= 1; off >>= 1)
        mw = fmaxf(mw, __shfl_xor_sync(0xffffffffu, mw, off));
    float ex = (tid < SS) ? __expf(lg - mw) : 0.f;
    float sw = ex;
    #pragma unroll
    for (int off = 16; off >= 1; off >>= 1)
        sw += __shfl_xor_sync(0xffffffffu, sw, off);
    if (lane == 0) { redm[tid >> 5] = mw; reds[tid >> 5] = sw; }
    __syncthreads();
    float mx = redm[0];
    #pragma unroll
    for (int w = 1; w < 8; w++) mx = fmaxf(mx, redm[w]);
    float den = 0.f;
    #pragma unroll
    for (int w = 0; w < 8; w++) den += reds[w] * __expf(redm[w] - mx);
    if (tid < SS) logits[tid] = ex * __expf(mw - mx);  // globally-referenced score
    __syncthreads();

    // ---- phase D: hagg[d] = sum_s score*h / den ----
    {
        const int d = tid & 63, c = tid >> 6;
        const int sp0 = c * 25;
        float acc = 0.f;
        #pragma unroll 5
        for (int sp = sp0; sp < sp0 + 25; sp++) {
            const float2 sc = *(const float2*)&logits[2 * sp];  // warp-broadcast
            const float2 f  = __half22float2(tile[sp * TSTR + d]);
            acc += sc.x * f.x + sc.y * f.y;
        }
        red[tid] = acc;
    }
    __syncthreads();
    if (tid < DD)
        haggsh[tid] = (red[tid] + red[64 + tid] + red[128 + tid] + red[192 + tid]) / den;
    __syncthreads();

    // ---- phase E: head + per-row loss ----
    if (tid < 32) {
        const float hl = haggsh[tid], hh = haggsh[tid + 32];
        float a0 = g_F[tid]      * hl + g_F[tid + 32] * hh;
        float a1 = g_F[64 + tid] * hl + g_F[96 + tid] * hh;
        #pragma unroll
        for (int off = 16; off >= 1; off >>= 1) {
            a0 += __shfl_xor_sync(0xffffffffu, a0, off);
            a1 += __shfl_xor_sync(0xffffffffu, a1, off);
        }
        if (tid == 0) {
            const float o0  = a0 + g_f0[0];
            const float o1  = a1 + g_f0[1];
            const int   lab = label[b];
            const float mo  = fmaxf(o0, o1);
            const float lse = mo + logf(__expf(o0 - mo) + __expf(o1 - mo));
            g_loss[b] = lse - (lab ? o1 : o0);
        }
    }

    // ---- tail: last block reduces (deterministic fixed-order sum) ----
    if (tid == 0) {
        __threadfence();
        const unsigned p = atomicAdd(&g_cnt, 1u);
        flag_sh = (p == BB - 1u) ? 1 : 0;
    }
    __syncthreads();
    if (flag_sh) {
        float acc = 0.f;
        for (int i = tid; i < BB; i += 256) acc += __ldcg(&g_loss[i]);
        red[tid] = acc;
        __syncthreads();
        #pragma unroll
        for (int off = 128; off >= 1; off >>= 1) {
            if (tid < off) red[tid] += red[tid + off];
            __syncthreads();
        }
        if (tid == 0) out[0] = red[0] / (float)BB;
    }
}

extern "C" void kernel_launch(void* const* d_in, const int* in_sizes, int n_in,
                              void* d_out, int out_size)
{
    const int*   hist  = (const int*)  d_in[0];
    const int*   cand  = (const int*)  d_in[1];
    const int*   label = (const int*)  d_in[2];
    const float* emb   = (const float*)d_in[3];
    const float* Wq    = (const float*)d_in[4];
    const float* bq    = (const float*)d_in[5];
    const float* Wk    = (const float*)d_in[6];
    const float* bk    = (const float*)d_in[7];
    const float* Wv    = (const float*)d_in[8];
    const float* bv    = (const float*)d_in[9];
    const float* Wp    = (const float*)d_in[10];
    const float* bp    = (const float*)d_in[11];
    const float* Wc    = (const float*)d_in[12];
    const float* bc    = (const float*)d_in[13];

    const int qsmem = 16768 * (int)sizeof(float);  // 67072 B
    cudaFuncSetAttribute(crec_qprep, cudaFuncAttributeMaxDynamicSharedMemorySize, qsmem);

    crec_qprep<<<QGRID, 512, qsmem>>>(cand, emb, Wq, bq, Wk, bk, Wv, bv, Wp, bp, Wc, bc);
    crec_main<<<BB, 256>>>(hist, label, emb, (float*)d_out);
}

// round 6
// speedup vs baseline: 2.7850x; 1.0200x over previous
#include <cuda_runtime.h>
#include <cuda_fp16.h>
#include <math.h>

#define BB    8192
#define SS    200
#define SP    100               // s-pairs
#define DD    64
#define NUM   100000
#define TSTR  68                // tile row stride in half2 words
#define NEGV  (-4294967296.0f)  // -2^32
#define LSC   1024.0f           // logit scaling for fp16 dot
#define QROWS 64
#define QGRID (BB / QROWS)      // 128

__device__ uint4    g_embh[NUM * 8];  // fp16 embedding table, 12.8 MB (row 0 zeroed)
__device__ float    g_mrow[BB * DD];
__device__ float    g_mc[BB];
__device__ float    g_F[2 * DD];
__device__ float    g_f0[2];
__device__ float    g_loss[BB];
__device__ unsigned g_cnt;

// ---------------- fp16 table build: 800000 threads, 8 floats each ----------------
__global__ __launch_bounds__(256) void crec_h16(const float* __restrict__ emb)
{
    const int t = blockIdx.x * 256 + threadIdx.x;
    if (t >= NUM * 8) return;
    const float4* __restrict__ e4 = (const float4*)emb;
    const float4 a = e4[2 * t], b = e4[2 * t + 1];
    uint4 o;
    half2 h;
    h = __floats2half2_rn(a.x, a.y); o.x = *(unsigned*)&h;
    h = __floats2half2_rn(a.z, a.w); o.y = *(unsigned*)&h;
    h = __floats2half2_rn(b.x, b.y); o.z = *(unsigned*)&h;
    h = __floats2half2_rn(b.z, b.w); o.w = *(unsigned*)&h;
    if (t < 8) o = make_uint4(0u, 0u, 0u, 0u);  // padding_idx=0
    g_embh[t] = o;
}

// ---------------- qprep: 128 blocks x 512 threads, 64 rows/block ----------------
extern __shared__ float dynsm[];
__global__ __launch_bounds__(512) void crec_qprep(
    const int*   __restrict__ cand, const float* __restrict__ emb,
    const float* __restrict__ Wq, const float* __restrict__ bq,
    const float* __restrict__ Wk, const float* __restrict__ bk,
    const float* __restrict__ Wv, const float* __restrict__ bv,
    const float* __restrict__ Wp, const float* __restrict__ bp,
    const float* __restrict__ Wc, const float* __restrict__ bc)
{
    float* WqT  = dynsm;           // [64*65]
    float* Wks  = dynsm + 4160;    // [64*64]
    float* csh  = dynsm + 8256;    // [8][64][8]
    float* qsh  = dynsm + 12352;   // [8][64][8]
    float* bqs  = dynsm + 16448;
    float* bks  = dynsm + 16512;
    float* cred = dynsm + 16576;   // [8][2][8]
    int*   cish = (int*)(dynsm + 16704); // [64]

    const int tid = threadIdx.x;
    const int d   = tid & 63, g = tid >> 6;
    const int rowbase = blockIdx.x * QROWS + g * 8;

    for (int x = tid; x < 4096; x += 512) {
        const int r = x >> 6, c = x & 63;
        WqT[c * 65 + r] = Wq[x];
        Wks[x]          = Wk[x];
    }
    if (tid < 64) { bqs[tid] = bq[tid]; bks[tid] = bk[tid]; }
    if (tid >= 64 && tid < 64 + QROWS) cish[tid - 64] = cand[blockIdx.x * QROWS + (tid - 64)];
    __syncthreads();

    #pragma unroll
    for (int r = 0; r < 8; r++) {
        const int ci = cish[g * 8 + r];
        csh[g * 512 + d * 8 + r] = (ci != 0) ? emb[ci * DD + d] : 0.f;
    }
    __syncthreads();

    float acc[8];
    #pragma unroll
    for (int r = 0; r < 8; r++) acc[r] = bqs[d];
    #pragma unroll 4
    for (int j = 0; j < 64; j++) {
        const float  w  = WqT[j * 65 + d];
        const float4 cA = *(const float4*)&csh[g * 512 + j * 8];
        const float4 cB = *(const float4*)&csh[g * 512 + j * 8 + 4];
        acc[0] += w * cA.x; acc[1] += w * cA.y; acc[2] += w * cA.z; acc[3] += w * cA.w;
        acc[4] += w * cB.x; acc[5] += w * cB.y; acc[6] += w * cB.z; acc[7] += w * cB.w;
    }
    *(float4*)&qsh[g * 512 + d * 8]     = make_float4(acc[0], acc[1], acc[2], acc[3]);
    *(float4*)&qsh[g * 512 + d * 8 + 4] = make_float4(acc[4], acc[5], acc[6], acc[7]);
    {
        const float bkd = bks[d];
        #pragma unroll
        for (int r = 0; r < 8; r++) {
            float p = bkd * acc[r];
            #pragma unroll
            for (int off = 16; off >= 1; off >>= 1) p += __shfl_xor_sync(0xffffffffu, p, off);
            if ((d & 31) == 0) cred[g * 16 + (d >> 5) * 8 + r] = p;
        }
    }
    __syncthreads();
    if (d < 8) g_mc[rowbase + d] = cred[g * 16 + d] + cred[g * 16 + 8 + d];

    float m[8];
    #pragma unroll
    for (int r = 0; r < 8; r++) m[r] = 0.f;
    #pragma unroll 4
    for (int i = 0; i < 64; i++) {
        const float  w  = Wks[i * 64 + d];
        const float4 qA = *(const float4*)&qsh[g * 512 + i * 8];
        const float4 qB = *(const float4*)&qsh[g * 512 + i * 8 + 4];
        m[0] += w * qA.x; m[1] += w * qA.y; m[2] += w * qA.z; m[3] += w * qA.w;
        m[4] += w * qB.x; m[5] += w * qB.y; m[6] += w * qB.z; m[7] += w * qB.w;
    }
    #pragma unroll
    for (int r = 0; r < 8; r++) g_mrow[(rowbase + r) * DD + d] = m[r];

    if (blockIdx.x == 0) {
        __syncthreads();
        float* Gsh = csh;
        float* wsh = csh + 128;
        if (tid < 128) {
            const int k = tid >> 6, j = tid & 63;
            float a = 0.f;
            #pragma unroll 8
            for (int i = 0; i < DD; i++) a += Wc[k * DD + i] * Wp[i * DD + j];
            Gsh[tid] = a;
        }
        if (tid >= 128 && tid < 192) {
            const int i = tid - 128;
            float a = 0.f;
            #pragma unroll 8
            for (int j = 0; j < DD; j++) a += Wp[i * DD + j] * bv[j];
            wsh[i] = a;
        }
        __syncthreads();
        if (tid < 128) {
            const int k = tid >> 6, dd = tid & 63;
            float a = 0.f;
            #pragma unroll 8
            for (int j = 0; j < DD; j++) a += Gsh[k * DD + j] * Wv[j * DD + dd];
            g_F[tid] = a;
        }
        if (tid == 192 || tid == 193) {
            const int k = tid - 192;
            float a = bc[k];
            for (int i = 0; i < DD; i++) a += Wc[k * DD + i] * (wsh[i] + bp[i]);
            g_f0[k] = a;
        }
        if (tid == 0) g_cnt = 0u;
    }
}

// ---------------- main ----------------
__global__ __launch_bounds__(256) void crec_main(
    const int*   __restrict__ hist, const int* __restrict__ label,
    float* __restrict__ out)
{
    __shared__ __align__(16) __half2 tile[SP * TSTR];  // 27200 B, pair-major
    __shared__ __align__(16) float   pool[256];
    __shared__ __align__(8)  float   logits[SS];
    __shared__ float msh[DD], haggsh[DD];
    __shared__ float redm[8], reds[8];
    __shared__ float ccsh;
    __shared__ int   flag_sh;

    int*   hidx = (int*)pool;
    float* red  = pool;

    const int b    = blockIdx.x;
    const int tid  = threadIdx.x;
    const int lane = tid & 31;

    // ---- phase A ----
    if (tid < SS) hidx[tid] = hist[b * SS + tid];
    if (tid < DD) msh[tid] = g_mrow[b * DD + tid];
    if (tid == 254) ccsh = g_mc[b];
    __syncthreads();

    // ---- phase B: fp16 gather + PRMT interleave + HFMA2 logits ----
    {
        const int q = tid & 7;                     // lane's 16B chunk: dims 8q..8q+7
        half2 mh[8];
        #pragma unroll
        for (int j = 0; j < 8; j++) {
            const __half hm = __float2half_rn(msh[8 * q + j] * LSC);
            mh[j] = __half2half2(hm);
        }
        const float cc = ccsh;

        for (int sp = tid >> 3; sp < SP; sp += 32) {
            const int  s0 = 2 * sp;
            const int2 ii = *(const int2*)&hidx[s0];
            const uint4 r0 = g_embh[ii.x * 8 + q];   // row 0 of table is zeros
            const uint4 r1 = g_embh[ii.y * 8 + q];

            // interleave halves: o_d = half2(row0[d], row1[d])
            unsigned o0 = __byte_perm(r0.x, r1.x, 0x5410);
            unsigned o1 = __byte_perm(r0.x, r1.x, 0x7632);
            unsigned o2 = __byte_perm(r0.y, r1.y, 0x5410);
            unsigned o3 = __byte_perm(r0.y, r1.y, 0x7632);
            unsigned o4 = __byte_perm(r0.z, r1.z, 0x5410);
            unsigned o5 = __byte_perm(r0.z, r1.z, 0x7632);
            unsigned o6 = __byte_perm(r0.w, r1.w, 0x5410);
            unsigned o7 = __byte_perm(r0.w, r1.w, 0x7632);
            *(uint4*)&tile[sp * TSTR + 8 * q]     = make_uint4(o0, o1, o2, o3);
            *(uint4*)&tile[sp * TSTR + 8 * q + 4] = make_uint4(o4, o5, o6, o7);

            // dual-sequence dot in half2 (scaled by LSC)
            half2 p = __floats2half2_rn(0.f, 0.f);
            p = __hfma2(*(half2*)&o0, mh[0], p);
            p = __hfma2(*(half2*)&o1, mh[1], p);
            p = __hfma2(*(half2*)&o2, mh[2], p);
            p = __hfma2(*(half2*)&o3, mh[3], p);
            p = __hfma2(*(half2*)&o4, mh[4], p);
            p = __hfma2(*(half2*)&o5, mh[5], p);
            p = __hfma2(*(half2*)&o6, mh[6], p);
            p = __hfma2(*(half2*)&o7, mh[7], p);
            #pragma unroll
            for (int off = 4; off >= 1; off >>= 1) {
                unsigned pu = *(unsigned*)&p;
                pu = __shfl_xor_sync(0xffffffffu, pu, off);
                p  = __hadd2(p, *(half2*)&pu);
            }
            if (q == 0) {
                const float2 pf = __half22float2(p);
                float l0 = pf.x * (1.0f / LSC) + cc; if (ii.x == 0) l0 *= NEGV;
                float l1 = pf.y * (1.0f / LSC) + cc; if (ii.y == 0) l1 *= NEGV;
                *(float2*)&logits[s0] = make_float2(l0, l1);
            }
        }
    }
    __syncthreads();

    // ---- phase C: single-round softmax ----
    const float lg = (tid < SS) ? logits[tid] : -INFINITY;
    float mw = lg;
    #pragma unroll
    for (int off = 16; off >= 1; off >>= 1)
        mw = fmaxf(mw, __shfl_xor_sync(0xffffffffu, mw, off));
    float ex = (tid < SS) ? __expf(lg - mw) : 0.f;
    float sw = ex;
    #pragma unroll
    for (int off = 16; off >= 1; off >>= 1)
        sw += __shfl_xor_sync(0xffffffffu, sw, off);
    if (lane == 0) { redm[tid >> 5] = mw; reds[tid >> 5] = sw; }
    __syncthreads();
    float mx = redm[0];
    #pragma unroll
    for (int w = 1; w < 8; w++) mx = fmaxf(mx, redm[w]);
    float den = 0.f;
    #pragma unroll
    for (int w = 0; w < 8; w++) den += reds[w] * __expf(redm[w] - mx);
    if (tid < SS) logits[tid] = ex * __expf(mw - mx);
    __syncthreads();

    // ---- phase D: hagg ----
    {
        const int d = tid & 63, c = tid >> 6;
        const int sp0 = c * 25;
        float acc = 0.f;
        #pragma unroll 5
        for (int sp = sp0; sp < sp0 + 25; sp++) {
            const float2 sc = *(const float2*)&logits[2 * sp];
            const float2 f  = __half22float2(tile[sp * TSTR + d]);
            acc += sc.x * f.x + sc.y * f.y;
        }
        red[tid] = acc;
    }
    __syncthreads();
    if (tid < DD)
        haggsh[tid] = (red[tid] + red[64 + tid] + red[128 + tid] + red[192 + tid]) / den;
    __syncthreads();

    // ---- phase E: head + loss ----
    if (tid < 32) {
        const float hl = haggsh[tid], hh = haggsh[tid + 32];
        float a0 = g_F[tid]      * hl + g_F[tid + 32] * hh;
        float a1 = g_F[64 + tid] * hl + g_F[96 + tid] * hh;
        #pragma unroll
        for (int off = 16; off >= 1; off >>= 1) {
            a0 += __shfl_xor_sync(0xffffffffu, a0, off);
            a1 += __shfl_xor_sync(0xffffffffu, a1, off);
        }
        if (tid == 0) {
            const float o0  = a0 + g_f0[0];
            const float o1  = a1 + g_f0[1];
            const int   lab = label[b];
            const float mo  = fmaxf(o0, o1);
            const float lse = mo + logf(__expf(o0 - mo) + __expf(o1 - mo));
            g_loss[b] = lse - (lab ? o1 : o0);
        }
    }

    // ---- tail reduce ----
    if (tid == 0) {
        __threadfence();
        const unsigned p = atomicAdd(&g_cnt, 1u);
        flag_sh = (p == BB - 1u) ? 1 : 0;
    }
    __syncthreads();
    if (flag_sh) {
        float acc = 0.f;
        for (int i = tid; i < BB; i += 256) acc += __ldcg(&g_loss[i]);
        red[tid] = acc;
        __syncthreads();
        #pragma unroll
        for (int off = 128; off >= 1; off >>= 1) {
            if (tid < off) red[tid] += red[tid + off];
            __syncthreads();
        }
        if (tid == 0) out[0] = red[0] / (float)BB;
    }
}

extern "C" void kernel_launch(void* const* d_in, const int* in_sizes, int n_in,
                              void* d_out, int out_size)
{
    const int*   hist  = (const int*)  d_in[0];
    const int*   cand  = (const int*)  d_in[1];
    const int*   label = (const int*)  d_in[2];
    const float* emb   = (const float*)d_in[3];
    const float* Wq    = (const float*)d_in[4];
    const float* bq    = (const float*)d_in[5];
    const float* Wk    = (const float*)d_in[6];
    const float* bk    = (const float*)d_in[7];
    const float* Wv    = (const float*)d_in[8];
    const float* bv    = (const float*)d_in[9];
    const float* Wp    = (const float*)d_in[10];
    const float* bp    = (const float*)d_in[11];
    const float* Wc    = (const float*)d_in[12];
    const float* bc    = (const float*)d_in[13];

    const int qsmem = 16768 * (int)sizeof(float);
    cudaFuncSetAttribute(crec_qprep, cudaFuncAttributeMaxDynamicSharedMemorySize, qsmem);

    crec_h16<<<(NUM * 8 + 255) / 256, 256>>>(emb);
    crec_qprep<<<QGRID, 512, qsmem>>>(cand, emb, Wq, bq, Wk, bk, Wv, bv, Wp, bp, Wc, bc);
    crec_main<<<BB, 256>>>(hist, label, (float*)d_out);
}